// round 15
// baseline (speedup 1.0000x reference)
#include <cuda_runtime.h>
#include <stdint.h>

#define BATCH 1024
#define KSEL  64
#define IFEAT 4096
#define OFEAT 4096

// Static device scratch (no runtime alloc).
__device__ float g_WT[(size_t)IFEAT * OFEAT];   // 64 MB, W transposed

// ---------------------------------------------------------------------------
// Transpose W (O,I) -> WT (I,O). 64x64 tiles, float4 both sides (proven ~22us).
// ---------------------------------------------------------------------------
__global__ __launch_bounds__(256) void transpose_kernel(const float* __restrict__ W)
{
    __shared__ float t[64][65];
    const int bc = blockIdx.x * 64;
    const int br = blockIdx.y * 64;
    const int tid = threadIdx.x;
    const int sub = tid & 15;
    const int grp = tid >> 4;
#pragma unroll
    for (int p = 0; p < 4; ++p) {
        int row = p * 16 + grp;
        int c4  = sub * 4;
        float4 v = *reinterpret_cast<const float4*>(
            W + (size_t)(br + row) * IFEAT + bc + c4);
        t[c4 + 0][row] = v.x;
        t[c4 + 1][row] = v.y;
        t[c4 + 2][row] = v.z;
        t[c4 + 3][row] = v.w;
    }
    __syncthreads();
#pragma unroll
    for (int p = 0; p < 4; ++p) {
        int c  = p * 16 + grp;
        int o4 = sub * 4;
        float4 v = make_float4(t[c][o4], t[c][o4 + 1], t[c][o4 + 2], t[c][o4 + 3]);
        *reinterpret_cast<float4*>(g_WT + (size_t)(bc + c) * OFEAT + br + o4) = v;
    }
}

// ---------------------------------------------------------------------------
// Monotone key helpers.
// ---------------------------------------------------------------------------
__device__ __forceinline__ unsigned f2u(float f) {
    unsigned u = __float_as_uint(f);
    return (u & 0x80000000u) ? ~u : (u | 0x80000000u);
}
__device__ __forceinline__ float u2f(unsigned u) {
    unsigned b = (u & 0x80000000u) ? (u ^ 0x80000000u) : ~u;
    return __uint_as_float(b);
}

// ---------------------------------------------------------------------------
// Fused per-sample gemv + exact top-64 via rank-by-counting.
// 512 threads; thread t owns outputs [8t, 8t+8) (two float4 per k-iteration
// -> 2x MLP vs R14). Exact sequential-k FMA chain per output, bias last.
// Then: 2-pass radix -> P16, warp-aggregated compaction, rank-by-counting
// scatter. Output identical to stable jax.lax.top_k (value desc, index asc).
// ---------------------------------------------------------------------------
__global__ __launch_bounds__(512) void gemv_topk_kernel(const float* __restrict__ x,
                                                        const int*   __restrict__ idx,
                                                        const float* __restrict__ bias,
                                                        float* __restrict__ out,
                                                        int out_size)
{
    __shared__ float sx[KSEL];
    __shared__ int   soff[KSEL];
    __shared__ unsigned hist[256];
    __shared__ unsigned long long cand[256];
    __shared__ unsigned sh_bin;
    __shared__ int sh_need;
    __shared__ int ncand;

    const int b   = blockIdx.x;
    const int tid = threadIdx.x;
    const int warp = tid >> 5, lane = tid & 31;
    const int o   = tid * 8;

    if (tid < KSEL) {
        sx[tid]   = x[b * KSEL + tid];
        soff[tid] = idx[b * KSEL + tid] * OFEAT;
    }
    __syncthreads();

    // --- gemv: 8 outputs/thread (2 x float4), exact chain per output ---
    float4 a0 = make_float4(0.f, 0.f, 0.f, 0.f);
    float4 a1 = make_float4(0.f, 0.f, 0.f, 0.f);
#pragma unroll 8
    for (int k = 0; k < KSEL; ++k) {
        const float xv = sx[k];
        const float4* wp = reinterpret_cast<const float4*>(g_WT + soff[k] + o);
        const float4 w0 = wp[0];
        const float4 w1 = wp[1];
        a0.x = fmaf(xv, w0.x, a0.x);
        a0.y = fmaf(xv, w0.y, a0.y);
        a0.z = fmaf(xv, w0.z, a0.z);
        a0.w = fmaf(xv, w0.w, a0.w);
        a1.x = fmaf(xv, w1.x, a1.x);
        a1.y = fmaf(xv, w1.y, a1.y);
        a1.z = fmaf(xv, w1.z, a1.z);
        a1.w = fmaf(xv, w1.w, a1.w);
    }
    const float4* bp = reinterpret_cast<const float4*>(bias + o);
    const float4 b0 = bp[0], b1 = bp[1];
    unsigned u[8];
    u[0] = f2u(a0.x + b0.x);
    u[1] = f2u(a0.y + b0.y);
    u[2] = f2u(a0.z + b0.z);
    u[3] = f2u(a0.w + b0.w);
    u[4] = f2u(a1.x + b1.x);
    u[5] = f2u(a1.y + b1.y);
    u[6] = f2u(a1.z + b1.z);
    u[7] = f2u(a1.w + b1.w);

    // --- 2-pass radix select of the 16-bit prefix containing rank-64 ---
    unsigned prefix = 0;
    int need = KSEL;
#pragma unroll
    for (int pass = 0; pass < 2; ++pass) {
        if (tid < 256) hist[tid] = 0;
        __syncthreads();
        if (pass == 0) {
#pragma unroll
            for (int j = 0; j < 8; ++j)
                atomicAdd(&hist[u[j] >> 24], 1u);
        } else {
#pragma unroll
            for (int j = 0; j < 8; ++j)
                if ((u[j] >> 24) == prefix)
                    atomicAdd(&hist[(u[j] >> 16) & 255], 1u);
        }
        __syncthreads();
        if (warp == 0) {
            int s = 0;
#pragma unroll
            for (int j = 0; j < 8; ++j) s += (int)hist[lane * 8 + j];
            int S = s;
#pragma unroll
            for (int off = 1; off < 32; off <<= 1) {
                int v = __shfl_down_sync(0xFFFFFFFFu, S, off);
                if (lane + off < 32) S += v;
            }
            int Snext = __shfl_down_sync(0xFFFFFFFFu, S, 1);
            if (lane == 31) Snext = 0;
            unsigned m = __ballot_sync(0xFFFFFFFFu, S >= need);
            int lc = 31 - __clz(m);
            if (lane == lc) {
                int cum = Snext;
                for (int bin = lc * 8 + 7; bin >= lc * 8; --bin) {
                    cum += (int)hist[bin];
                    if (cum >= need) {
                        sh_bin  = (unsigned)bin;
                        sh_need = need - (cum - (int)hist[bin]);
                        break;
                    }
                }
            }
        }
        __syncthreads();
        prefix = (prefix << 8) | sh_bin;
        need   = sh_need;
        __syncthreads();
    }
    const unsigned P16 = prefix;

    // --- Warp-aggregated candidate compaction ---
    if (tid == 0) ncand = 0;
    __syncthreads();
    {
        bool pr[8];
        int myc = 0;
#pragma unroll
        for (int j = 0; j < 8; ++j) {
            pr[j] = ((u[j] >> 16) >= P16);
            myc += pr[j] ? 1 : 0;
        }
        int inc = myc;
#pragma unroll
        for (int d = 1; d < 32; d <<= 1) {
            int v = __shfl_up_sync(0xFFFFFFFFu, inc, d);
            if (lane >= d) inc += v;
        }
        int excl = inc - myc;
        int wtot = __shfl_sync(0xFFFFFFFFu, inc, 31);
        int wb = 0;
        if (lane == 31 && wtot > 0) wb = atomicAdd(&ncand, wtot);
        wb = __shfl_sync(0xFFFFFFFFu, wb, 31);
        int pos = wb + excl;
#pragma unroll
        for (int j = 0; j < 8; ++j) {
            if (pr[j] && pos < 256) {
                int oo = o + j;
                cand[pos++] = ((unsigned long long)u[j] << 32) | (unsigned)(4095 - oo);
            }
        }
    }
    __syncthreads();

    // --- Rank by counting (keys unique -> ranks unique), direct scatter ---
    const int n = (ncand < 256) ? ncand : 256;
    if (tid < n) {
        const unsigned long long my = cand[tid];
        int rank = 0;
        for (int i = 0; i < n; ++i)
            rank += (cand[i] > my) ? 1 : 0;
        if (rank < KSEL) {
            unsigned uu = (unsigned)(my >> 32);
            int oo = 4095 - (int)(my & 0xFFFFFFFFull);
            int half = out_size >> 1;
            out[(size_t)b * KSEL + rank]        = u2f(uu);
            out[(size_t)half + b * KSEL + rank] = (float)oo;
        }
    }
}

// ---------------------------------------------------------------------------
extern "C" void kernel_launch(void* const* d_in, const int* in_sizes, int n_in,
                              void* d_out, int out_size)
{
    const float* input  = nullptr;
    const float* weight = nullptr;
    const float* bias   = nullptr;
    const int*   idx    = nullptr;
    for (int i = 0; i < n_in; ++i) {
        if (in_sizes[i] == OFEAT * IFEAT)      weight = (const float*)d_in[i];
        else if (in_sizes[i] == OFEAT)         bias   = (const float*)d_in[i];
        else if (in_sizes[i] == BATCH * KSEL) {
            if (!input) input = (const float*)d_in[i];
            else        idx   = (const int*)d_in[i];
        }
    }

    transpose_kernel<<<dim3(IFEAT / 64, OFEAT / 64), 256>>>(weight);
    gemv_topk_kernel<<<BATCH, 512>>>(input, idx, bias, (float*)d_out, out_size);
}

// round 16
// speedup vs baseline: 1.1356x; 1.1356x over previous
#include <cuda_runtime.h>
#include <stdint.h>

#define BATCH 1024
#define KSEL  64
#define IFEAT 4096
#define OFEAT 4096

// Static device scratch (no runtime alloc).
__device__ float g_WT[(size_t)IFEAT * OFEAT];   // 64 MB, W transposed

// ---------------------------------------------------------------------------
// Transpose W (O,I) -> WT (I,O). 64x64 tiles, float4 both sides (proven ~22us).
// ---------------------------------------------------------------------------
__global__ __launch_bounds__(256) void transpose_kernel(const float* __restrict__ W)
{
    __shared__ float t[64][65];
    const int bc = blockIdx.x * 64;
    const int br = blockIdx.y * 64;
    const int tid = threadIdx.x;
    const int sub = tid & 15;
    const int grp = tid >> 4;
#pragma unroll
    for (int p = 0; p < 4; ++p) {
        int row = p * 16 + grp;
        int c4  = sub * 4;
        float4 v = *reinterpret_cast<const float4*>(
            W + (size_t)(br + row) * IFEAT + bc + c4);
        t[c4 + 0][row] = v.x;
        t[c4 + 1][row] = v.y;
        t[c4 + 2][row] = v.z;
        t[c4 + 3][row] = v.w;
    }
    __syncthreads();
#pragma unroll
    for (int p = 0; p < 4; ++p) {
        int c  = p * 16 + grp;
        int o4 = sub * 4;
        float4 v = make_float4(t[c][o4], t[c][o4 + 1], t[c][o4 + 2], t[c][o4 + 3]);
        *reinterpret_cast<float4*>(g_WT + (size_t)(bc + c) * OFEAT + br + o4) = v;
    }
}

// ---------------------------------------------------------------------------
// Monotone key helpers.
// ---------------------------------------------------------------------------
__device__ __forceinline__ unsigned f2u(float f) {
    unsigned u = __float_as_uint(f);
    return (u & 0x80000000u) ? ~u : (u | 0x80000000u);
}
__device__ __forceinline__ float u2f(unsigned u) {
    unsigned b = (u & 0x80000000u) ? (u ^ 0x80000000u) : ~u;
    return __uint_as_float(b);
}

// ---------------------------------------------------------------------------
// Fused per-sample gemv + exact top-64 via rank-by-counting.
// 1024 threads; thread t owns outputs [4t, 4t+4): exact sequential-k FMA
// chain, bias last (bit-exact vs reference einsum + bias).
// Hot loop: one LDS.64 (packed x|byte-offset) + one LDG.128 + 4 FFMA per k.
// Select: 2-pass radix -> P16, warp-aggregated compaction, rank-by-counting
// scatter. Output identical to stable jax.lax.top_k (value desc, index asc).
// ---------------------------------------------------------------------------
__global__ __launch_bounds__(1024) void gemv_topk_kernel(const float* __restrict__ x,
                                                         const int*   __restrict__ idx,
                                                         const float* __restrict__ bias,
                                                         float* __restrict__ out,
                                                         int out_size)
{
    __shared__ uint2 sent[KSEL];    // (.x = x bits, .y = row byte offset)
    __shared__ unsigned hist[256];
    __shared__ unsigned long long cand[256];
    __shared__ unsigned sh_bin;
    __shared__ int sh_need;
    __shared__ int ncand;

    const int b   = blockIdx.x;
    const int tid = threadIdx.x;
    const int warp = tid >> 5, lane = tid & 31;
    const int o   = tid * 4;

    if (tid < KSEL) {
        sent[tid] = make_uint2(__float_as_uint(x[b * KSEL + tid]),
                               (unsigned)idx[b * KSEL + tid] * (OFEAT * 4u));
    }
    __syncthreads();

    // --- gemv: 4 outputs/thread, exact chain; base pointer precomputed ---
    const char* const wbase = reinterpret_cast<const char*>(g_WT) + (size_t)o * 4u;
    float4 a = make_float4(0.f, 0.f, 0.f, 0.f);
#pragma unroll 8
    for (int k = 0; k < KSEL; ++k) {
        const uint2 e = sent[k];                     // one LDS.64, broadcast
        const float xv = __uint_as_float(e.x);
        const float4 w = *reinterpret_cast<const float4*>(wbase + e.y);
        a.x = fmaf(xv, w.x, a.x);
        a.y = fmaf(xv, w.y, a.y);
        a.z = fmaf(xv, w.z, a.z);
        a.w = fmaf(xv, w.w, a.w);
    }
    const float4 bb = *reinterpret_cast<const float4*>(bias + o);
    unsigned u[4];
    u[0] = f2u(a.x + bb.x);
    u[1] = f2u(a.y + bb.y);
    u[2] = f2u(a.z + bb.z);
    u[3] = f2u(a.w + bb.w);

    // --- 2-pass radix select of the 16-bit prefix containing rank-64 ---
    unsigned prefix = 0;
    int need = KSEL;
#pragma unroll
    for (int pass = 0; pass < 2; ++pass) {
        if (tid < 256) hist[tid] = 0;
        __syncthreads();
        if (pass == 0) {
#pragma unroll
            for (int j = 0; j < 4; ++j)
                atomicAdd(&hist[u[j] >> 24], 1u);
        } else {
#pragma unroll
            for (int j = 0; j < 4; ++j)
                if ((u[j] >> 24) == prefix)
                    atomicAdd(&hist[(u[j] >> 16) & 255], 1u);
        }
        __syncthreads();
        if (warp == 0) {
            int s = 0;
#pragma unroll
            for (int j = 0; j < 8; ++j) s += (int)hist[lane * 8 + j];
            int S = s;
#pragma unroll
            for (int off = 1; off < 32; off <<= 1) {
                int v = __shfl_down_sync(0xFFFFFFFFu, S, off);
                if (lane + off < 32) S += v;
            }
            int Snext = __shfl_down_sync(0xFFFFFFFFu, S, 1);
            if (lane == 31) Snext = 0;
            unsigned m = __ballot_sync(0xFFFFFFFFu, S >= need);
            int lc = 31 - __clz(m);
            if (lane == lc) {
                int cum = Snext;
                for (int bin = lc * 8 + 7; bin >= lc * 8; --bin) {
                    cum += (int)hist[bin];
                    if (cum >= need) {
                        sh_bin  = (unsigned)bin;
                        sh_need = need - (cum - (int)hist[bin]);
                        break;
                    }
                }
            }
        }
        __syncthreads();
        prefix = (prefix << 8) | sh_bin;
        need   = sh_need;
        __syncthreads();
    }
    const unsigned P16 = prefix;

    // --- Warp-aggregated candidate compaction ---
    if (tid == 0) ncand = 0;
    __syncthreads();
    {
        bool pr[4];
        int myc = 0;
#pragma unroll
        for (int j = 0; j < 4; ++j) {
            pr[j] = ((u[j] >> 16) >= P16);
            myc += pr[j] ? 1 : 0;
        }
        int inc = myc;
#pragma unroll
        for (int d = 1; d < 32; d <<= 1) {
            int v = __shfl_up_sync(0xFFFFFFFFu, inc, d);
            if (lane >= d) inc += v;
        }
        int excl = inc - myc;
        int wtot = __shfl_sync(0xFFFFFFFFu, inc, 31);
        int wb = 0;
        if (lane == 31 && wtot > 0) wb = atomicAdd(&ncand, wtot);
        wb = __shfl_sync(0xFFFFFFFFu, wb, 31);
        int pos = wb + excl;
#pragma unroll
        for (int j = 0; j < 4; ++j) {
            if (pr[j] && pos < 256) {
                int oo = o + j;
                cand[pos++] = ((unsigned long long)u[j] << 32) | (unsigned)(4095 - oo);
            }
        }
    }
    __syncthreads();

    // --- Rank by counting (keys unique -> ranks unique), direct scatter ---
    const int n = (ncand < 256) ? ncand : 256;
    if (tid < n) {
        const unsigned long long my = cand[tid];
        int rank = 0;
        for (int i = 0; i < n; ++i)
            rank += (cand[i] > my) ? 1 : 0;
        if (rank < KSEL) {
            unsigned uu = (unsigned)(my >> 32);
            int oo = 4095 - (int)(my & 0xFFFFFFFFull);
            int half = out_size >> 1;
            out[(size_t)b * KSEL + rank]        = u2f(uu);
            out[(size_t)half + b * KSEL + rank] = (float)oo;
        }
    }
}

// ---------------------------------------------------------------------------
extern "C" void kernel_launch(void* const* d_in, const int* in_sizes, int n_in,
                              void* d_out, int out_size)
{
    const float* input  = nullptr;
    const float* weight = nullptr;
    const float* bias   = nullptr;
    const int*   idx    = nullptr;
    for (int i = 0; i < n_in; ++i) {
        if (in_sizes[i] == OFEAT * IFEAT)      weight = (const float*)d_in[i];
        else if (in_sizes[i] == OFEAT)         bias   = (const float*)d_in[i];
        else if (in_sizes[i] == BATCH * KSEL) {
            if (!input) input = (const float*)d_in[i];
            else        idx   = (const int*)d_in[i];
        }
    }

    transpose_kernel<<<dim3(IFEAT / 64, OFEAT / 64), 256>>>(weight);
    gemv_topk_kernel<<<BATCH, 1024>>>(input, idx, bias, (float*)d_out, out_size);
}